// round 2
// baseline (speedup 1.0000x reference)
#include <cuda_runtime.h>
#include <math.h>

// FullCliffordMeanField3DClassifier — collapsed algebra, 2-kernel pipeline.
//
// Algebra (validated R1, rel_err 3e-7):
//   pv = geoprod(pos,vel) nonzero comps {0: p.v, 4: p1v2-p2v1, 5: p1v3-p3v1, 6: p2v3-p3v2}
//   mean(geoprod(vel, mean_pv)) = geoprod(mean(vel), mean_pv)   (bilinearity)
//   interaction comps {1,2,3,7}:
//     i1 = V1*m0 - V2*m4 - V3*m5
//     i2 = V2*m0 + V1*m4 - V3*m6
//     i3 = V3*m0 + V1*m5 + V2*m6
//     i7 = V1*m6 - V2*m5 + V3*m4
//   MLP 8->64->64->2, exact-erf GELU; only W1 rows {1,2,3,7} contribute.
//
// Kernel A: 4096 CTAs stream x (100.7 MB) and write 7 partial sums per
//           (batch, slice) to static scratch.  Pure-load kernel, low regs.
// Kernel B: 1024 CTAs x 64 thr finish reduction + MLP.

#define THREADS  256
#define NPTS     4096
#define SPLIT    4
#define CHUNK    (NPTS / SPLIT)            // 1024 points per CTA
#define PAIRS    (CHUNK / 2)               // 512 pairs
#define PPT      (PAIRS / THREADS)         // 2 pairs per thread
#define MAXB     1024

__device__ float g_partial[MAXB * SPLIT * 8];   // [batch][slice][8]

__device__ __forceinline__ float gelu_exact(float v) {
    return 0.5f * v * (1.0f + erff(v * 0.70710678118654752440f));
}

// ---------------------------------------------------------------- kernel A
__global__ __launch_bounds__(THREADS)
void cm_reduce_kernel(const float* __restrict__ x)
{
    const int bb    = blockIdx.x;
    const int batch = bb / SPLIT;
    const int slice = bb % SPLIT;
    const int t     = threadIdx.x;

    const float4* __restrict__ base = reinterpret_cast<const float4*>(
        x + (size_t)batch * (size_t)(NPTS * 6) + (size_t)slice * (CHUNK * 6));

    float sdot = 0.f, s12 = 0.f, s13 = 0.f, s23 = 0.f;
    float sv1 = 0.f, sv2 = 0.f, sv3 = 0.f;

    #pragma unroll
    for (int k = 0; k < PPT; ++k) {
        const int pi = t + k * THREADS;
        const float4 f0 = base[3 * pi + 0];   // p1a p2a p3a v1a
        const float4 f1 = base[3 * pi + 1];   // v2a v3a p1b p2b
        const float4 f2 = base[3 * pi + 2];   // p3b v1b v2b v3b

        // element a
        sdot += f0.x * f0.w + f0.y * f1.x + f0.z * f1.y;
        s12  += f0.x * f1.x - f0.y * f0.w;
        s13  += f0.x * f1.y - f0.z * f0.w;
        s23  += f0.y * f1.y - f0.z * f1.x;
        sv1  += f0.w; sv2 += f1.x; sv3 += f1.y;
        // element b
        sdot += f1.z * f2.y + f1.w * f2.z + f2.x * f2.w;
        s12  += f1.z * f2.z - f1.w * f2.y;
        s13  += f1.z * f2.w - f2.x * f2.y;
        s23  += f1.w * f2.w - f2.x * f2.z;
        sv1  += f2.y; sv2 += f2.z; sv3 += f2.w;
    }

    // warp tree
    #pragma unroll
    for (int off = 16; off > 0; off >>= 1) {
        sdot += __shfl_xor_sync(0xffffffffu, sdot, off);
        s12  += __shfl_xor_sync(0xffffffffu, s12,  off);
        s13  += __shfl_xor_sync(0xffffffffu, s13,  off);
        s23  += __shfl_xor_sync(0xffffffffu, s23,  off);
        sv1  += __shfl_xor_sync(0xffffffffu, sv1,  off);
        sv2  += __shfl_xor_sync(0xffffffffu, sv2,  off);
        sv3  += __shfl_xor_sync(0xffffffffu, sv3,  off);
    }

    __shared__ float red[8][7];
    const int warp = t >> 5, lane = t & 31;
    if (lane == 0) {
        red[warp][0] = sdot; red[warp][1] = s12; red[warp][2] = s13;
        red[warp][3] = s23;  red[warp][4] = sv1; red[warp][5] = sv2;
        red[warp][6] = sv3;
    }
    __syncthreads();

    if (t == 0) {
        float r[7];
        #pragma unroll
        for (int j = 0; j < 7; ++j) {
            float a = red[0][j];
            #pragma unroll
            for (int w = 1; w < 8; ++w) a += red[w][j];
            r[j] = a;
        }
        float4* dst = reinterpret_cast<float4*>(&g_partial[bb * 8]);
        dst[0] = make_float4(r[0], r[1], r[2], r[3]);
        dst[1] = make_float4(r[4], r[5], r[6], 0.f);
    }
}

// ---------------------------------------------------------------- kernel B
__global__ __launch_bounds__(64)
void cm_mlp_kernel(
    const float* __restrict__ W1, const float* __restrict__ b1,
    const float* __restrict__ W2, const float* __restrict__ b2,
    const float* __restrict__ W3, const float* __restrict__ b3,
    float* __restrict__ out)
{
    const int batch = blockIdx.x;
    const int t     = threadIdx.x;

    __shared__ float ii[4];
    __shared__ float h1[64];
    __shared__ float h2[64];

    if (t < 32) {
        // lane s*8+j holds partial j of slice s  (SPLIT=4, 4*8=32 lanes)
        float v = g_partial[batch * (SPLIT * 8) + t];
        v += __shfl_xor_sync(0xffffffffu, v, 8);
        v += __shfl_xor_sync(0xffffffffu, v, 16);   // lanes 0..7 now hold totals
        // broadcast via shuffles into lane 0
        const float m0 = __shfl_sync(0xffffffffu, v, 0) * (1.0f / NPTS);
        const float m4 = __shfl_sync(0xffffffffu, v, 1) * (1.0f / NPTS);
        const float m5 = __shfl_sync(0xffffffffu, v, 2) * (1.0f / NPTS);
        const float m6 = __shfl_sync(0xffffffffu, v, 3) * (1.0f / NPTS);
        const float V1 = __shfl_sync(0xffffffffu, v, 4) * (1.0f / NPTS);
        const float V2 = __shfl_sync(0xffffffffu, v, 5) * (1.0f / NPTS);
        const float V3 = __shfl_sync(0xffffffffu, v, 6) * (1.0f / NPTS);
        if (t == 0) {
            ii[0] = V1 * m0 - V2 * m4 - V3 * m5;   // e1
            ii[1] = V2 * m0 + V1 * m4 - V3 * m6;   // e2
            ii[2] = V3 * m0 + V1 * m5 + V2 * m6;   // e3
            ii[3] = V1 * m6 - V2 * m5 + V3 * m4;   // e123
        }
    }
    __syncthreads();

    // layer 1 (W1 rows 1,2,3,7 only)
    {
        float a = b1[t];
        a += ii[0] * W1[1 * 64 + t];
        a += ii[1] * W1[2 * 64 + t];
        a += ii[2] * W1[3 * 64 + t];
        a += ii[3] * W1[7 * 64 + t];
        h1[t] = gelu_exact(a);
    }
    __syncthreads();

    // layer 2
    {
        float a = b2[t];
        #pragma unroll
        for (int i = 0; i < 64; ++i) a += h1[i] * W2[i * 64 + t];
        h2[t] = gelu_exact(a);
    }
    __syncthreads();

    // layer 3
    if (t < 2) {
        float a = b3[t];
        #pragma unroll
        for (int i = 0; i < 64; ++i) a += h2[i] * W3[i * 2 + t];
        out[batch * 2 + t] = a;
    }
}

// ---------------------------------------------------------------- launch
extern "C" void kernel_launch(void* const* d_in, const int* in_sizes, int n_in,
                              void* d_out, int out_size)
{
    const float* x  = (const float*)d_in[0];
    const float* W1 = (const float*)d_in[1];
    const float* b1 = (const float*)d_in[2];
    const float* W2 = (const float*)d_in[3];
    const float* b2 = (const float*)d_in[4];
    const float* W3 = (const float*)d_in[5];
    const float* b3 = (const float*)d_in[6];
    float* out = (float*)d_out;

    const int B = in_sizes[0] / (NPTS * 6);   // 1024

    cm_reduce_kernel<<<B * SPLIT, THREADS>>>(x);
    cm_mlp_kernel<<<B, 64>>>(W1, b1, W2, b2, W3, b3, out);
}